// round 16
// baseline (speedup 1.0000x reference)
#include <cuda_runtime.h>
#include <cuda_fp16.h>
#include <cstdint>

#define N_NODES 50000
#define N_EDGES 800000
#define NF 128
#define WTILE 16
#define NWTILES (N_EDGES / WTILE)   // 50000
#define NTHREADS 256
#define GRID 608                    // 4 CTAs/SM x 152 SMs
#define TOTWARPS (GRID * 8)         // 4864

#define S2_C 0.7071067811865475f
#define S2_3_C 0.4082482904638631f
#define INV_SQRT_MUL_C 0.17677669529663687f

// ---- shared memory layout (32-bit word offsets) ----
#define OFF_FB1 0            // 2kk x 8j x 32 lanes x uint2  = 1024 words
#define OFF_FB2 1024         // 4kk x 4j x 32 x uint2        = 1024
#define OFF_FB3 2048         // 2kk x 16j x 32 x uint2       = 2048 -> 4096
#define OFF_B1  4096         // 64 f32
#define OFF_B2  4160         // 32 f32
#define OFF_B3  4192         // 128 f32 -> 4320
#define OFF_SW  4320         // per-warp: 16 rows x 68 words = 1088 w; x8 -> 13024
                             // (first 320 words double as the per-warp SE staging area)
#define SW_WSTR 68
#define SE_WSTR 20
#define OFF_SRC 13024        // per-warp 16 ints  x8 -> 13152
#define OFF_DST 13152        // per-warp 16 ints  x8 -> 13280
#define OFF_EF  13280        // per-warp 16 float4 = 64 w x8 -> 13792
#define SMEM_WORDS 13792     // 55.2 KB -> 4 CTAs/SM

__device__ __forceinline__ float silu_f(float x) {
    return x * (1.0f / (1.0f + __expf(-x)));
}

__device__ __forceinline__ uint32_t pack_h2(float a, float b) {
    __half2 h = __floats2half2_rn(a, b);
    return *reinterpret_cast<uint32_t*>(&h);
}

__device__ __forceinline__ float2 h22f2(uint32_t u) {
    return __half22float2(*reinterpret_cast<__half2*>(&u));
}

__device__ __forceinline__ void mma_f16(float c[4],
                                        uint32_t a0, uint32_t a1, uint32_t a2, uint32_t a3,
                                        uint32_t b0, uint32_t b1) {
    asm volatile("mma.sync.aligned.m16n8k16.row.col.f32.f16.f16.f32 "
                 "{%0,%1,%2,%3},{%4,%5,%6,%7},{%8,%9},{%0,%1,%2,%3};"
                 : "+f"(c[0]), "+f"(c[1]), "+f"(c[2]), "+f"(c[3])
                 : "r"(a0), "r"(a1), "r"(a2), "r"(a3), "r"(b0), "r"(b1));
}

extern __shared__ float sm[];

__global__ __launch_bounds__(NTHREADS, 4)
void tfn_fused_kernel(const int* __restrict__ edge_index,
                      const float* __restrict__ node_feat,
                      const float* __restrict__ edge_feat,
                      const float* __restrict__ edge_embed,
                      const float* __restrict__ w1, const float* __restrict__ b1,
                      const float* __restrict__ w2, const float* __restrict__ b2,
                      const float* __restrict__ w3, const float* __restrict__ b3,
                      const float* __restrict__ sc_w0,
                      const float* __restrict__ sc_w1,
                      float* __restrict__ out)
{
    const int t = threadIdx.x;
    const int wu = t >> 5, lane = t & 31;
    const int g = lane >> 2, tig = lane & 3;
    uint32_t* smu = (uint32_t*)sm;

    // ---- precompute fp16 B-fragments (once per CTA) ----
    for (int i = t; i < 512; i += NTHREADS) {        // W1: 32x64, kk 0..1, j 0..7
        int kk = i >> 8, jg = (i >> 5) & 7, ln = i & 31;
        int gg = ln >> 2, tt = ln & 3;
        int k0 = 16*kk + 2*tt, n = 8*jg + gg;
        ((uint2*)&sm[OFF_FB1])[i] = make_uint2(
            pack_h2(w1[k0*64 + n],     w1[(k0+1)*64 + n]),
            pack_h2(w1[(k0+8)*64 + n], w1[(k0+9)*64 + n]));
    }
    for (int i = t; i < 512; i += NTHREADS) {        // W2: 64x32, kk 0..3, j 0..3
        int kk = i >> 7, jg = (i >> 5) & 3, ln = i & 31;
        int gg = ln >> 2, tt = ln & 3;
        int k0 = 16*kk + 2*tt, n = 8*jg + gg;
        ((uint2*)&sm[OFF_FB2])[i] = make_uint2(
            pack_h2(w2[k0*32 + n],     w2[(k0+1)*32 + n]),
            pack_h2(w2[(k0+8)*32 + n], w2[(k0+9)*32 + n]));
    }
    for (int i = t; i < 1024; i += NTHREADS) {       // W3: 32x128, kk 0..1, j 0..15
        int kk = i >> 9, jg = (i >> 5) & 15, ln = i & 31;
        int gg = ln >> 2, tt = ln & 3;
        int k0 = 16*kk + 2*tt, n = 8*jg + gg;
        ((uint2*)&sm[OFF_FB3])[i] = make_uint2(
            pack_h2(w3[k0*128 + n],     w3[(k0+1)*128 + n]),
            pack_h2(w3[(k0+8)*128 + n], w3[(k0+9)*128 + n]));
    }
    for (int i = t; i < 64;  i += NTHREADS) sm[OFF_B1 + i] = b1[i];
    for (int i = t; i < 32;  i += NTHREADS) sm[OFF_B2 + i] = b2[i];
    for (int i = t; i < 128; i += NTHREADS) sm[OFF_B3 + i] = b3[i];

    // ---- fused self-connection pass (atomic adds onto zeroed out) ----
    {
        const int half = t >> 7, ct = t & 127;
        float wreg[32]; int jsc = 0;
        if (ct < 32) {
            #pragma unroll
            for (int u = 0; u < 32; u++) wreg[u] = sc_w0[u * 32 + ct];
        } else {
            int m = ct - 32;
            int v = m / 3;
            jsc = m - 3 * v;
            #pragma unroll
            for (int u = 0; u < 32; u++) wreg[u] = sc_w1[u * 32 + v];
        }
        float* sxb = &sm[OFF_SW + half * 128];   // SW area unused until main loop
        const int bid1 = 1 + half;
        for (int n = 2 * (int)blockIdx.x + half; n < N_NODES; n += 2 * (int)gridDim.x) {
            asm volatile("bar.sync %0, %1;" :: "r"(bid1), "r"(128) : "memory");
            sxb[ct] = node_feat[(size_t)n * NF + ct];
            asm volatile("bar.sync %0, %1;" :: "r"(bid1), "r"(128) : "memory");
            float acc = 0.0f;
            if (ct < 32) {
                #pragma unroll
                for (int u = 0; u < 32; u++) acc += sxb[u] * wreg[u];
            } else {
                #pragma unroll
                for (int u = 0; u < 32; u++) acc += sxb[32 + 3*u + jsc] * wreg[u];
            }
            atomicAdd(&out[(size_t)n * NF + ct], acc * INV_SQRT_MUL_C);
        }
    }
    __syncthreads();   // FB/B visible; SW scratch free; warps fully independent after this

    // per-warp smem regions
    int* sSrcW = (int*)&sm[OFF_SRC + wu * 16];
    int* sDstW = (int*)&sm[OFF_DST + wu * 16];
    float4* sEFW = (float4*)&sm[OFF_EF + wu * 64];
    uint32_t* SWp = smu + OFF_SW + wu * (16 * SW_WSTR);
    uint32_t* SEp = SWp;            // SE staging unions with SW (disjoint lifetimes)

    // per-lane message constants
    const int c4 = 4 * lane;
    const int m0 = c4 - 32;
    const int ua = (lane >= 8) ? (m0 / 3) : 0;
    const int j0 = (lane >= 8) ? (m0 - 3 * ua) : 0;   // m0 mod 3, no division in loop
    const int srcA = (lane < 8) ? (8 + 3 * lane) : (ua >> 2);
    const int selid = ua & 3;

    const int gw = (int)blockIdx.x * 8 + wu;   // global warp id

    for (int wt = gw; wt < NWTILES; wt += TOTWARPS) {
        const int ebg = wt * WTILE;            // global edge base

        // ---- per-warp idx + edge_feat ----
        if (lane < 16) {
            sSrcW[lane] = edge_index[ebg + lane];
            sDstW[lane] = edge_index[N_EDGES + ebg + lane];
            sEFW[lane]  = ((const float4*)edge_feat)[ebg + lane];
        }

        // ---- stage embed tile (16x32) coalesced into per-warp SE, fp16-packed ----
        {
            const float4* E4 = (const float4*)(edge_embed + (size_t)ebg * 32);
            #pragma unroll
            for (int it = 0; it < 4; it++) {
                int idx = lane + 32 * it;      // 0..127 float4s, consecutive lanes adjacent
                float4 v = __ldg(&E4[idx]);
                int e = idx >> 3, k = idx & 7;
                *(uint2*)&SEp[e * SE_WSTR + 2 * k] =
                    make_uint2(pack_h2(v.x, v.y), pack_h2(v.z, v.w));
            }
        }
        __syncwarp();

        // ---- A1 fragments from per-warp SE (conflict-free stride-20 pattern) ----
        uint32_t A1[2][4];
        #pragma unroll
        for (int kk = 0; kk < 2; kk++) {
            const uint32_t* Ab = &SEp[g * SE_WSTR + 8*kk + tig];
            A1[kk][0] = Ab[0];
            A1[kk][1] = Ab[8 * SE_WSTR];
            A1[kk][2] = Ab[4];
            A1[kk][3] = Ab[8 * SE_WSTR + 4];
        }

        // ---- GEMM1: (16x32)@(32x64) -> silu -> A2 fragments (in registers) ----
        uint32_t A2[4][4];
        #pragma unroll
        for (int kk2 = 0; kk2 < 4; kk2++) {
            #pragma unroll
            for (int jj = 0; jj < 2; jj++) {
                const int j = 2*kk2 + jj;
                float c[4] = {0,0,0,0};
                uint2 b0 = ((const uint2*)&sm[OFF_FB1])[j*32 + lane];
                mma_f16(c, A1[0][0], A1[0][1], A1[0][2], A1[0][3], b0.x, b0.y);
                uint2 b1v = ((const uint2*)&sm[OFF_FB1])[(8 + j)*32 + lane];
                mma_f16(c, A1[1][0], A1[1][1], A1[1][2], A1[1][3], b1v.x, b1v.y);
                float2 bb = *(const float2*)&sm[OFF_B1 + 8*j + 2*tig];
                A2[kk2][2*jj]   = pack_h2(silu_f(c[0] + bb.x), silu_f(c[1] + bb.y));
                A2[kk2][2*jj+1] = pack_h2(silu_f(c[2] + bb.x), silu_f(c[3] + bb.y));
            }
        }

        // ---- GEMM2: (16x64)@(64x32) -> silu -> A3 fragments ----
        uint32_t A3[2][4];
        #pragma unroll
        for (int kk3 = 0; kk3 < 2; kk3++) {
            #pragma unroll
            for (int jj = 0; jj < 2; jj++) {
                const int j = 2*kk3 + jj;
                float c[4] = {0,0,0,0};
                #pragma unroll
                for (int kk = 0; kk < 4; kk++) {
                    uint2 b = ((const uint2*)&sm[OFF_FB2])[(kk*4 + j)*32 + lane];
                    mma_f16(c, A2[kk][0], A2[kk][1], A2[kk][2], A2[kk][3], b.x, b.y);
                }
                float2 bb = *(const float2*)&sm[OFF_B2 + 8*j + 2*tig];
                A3[kk3][2*jj]   = pack_h2(silu_f(c[0] + bb.x), silu_f(c[1] + bb.y));
                A3[kk3][2*jj+1] = pack_h2(silu_f(c[2] + bb.x), silu_f(c[3] + bb.y));
            }
        }

        // ---- first gather batch (edges 0..7) ----
        uint2 xhA[8];
        #pragma unroll
        for (int i = 0; i < 8; i++) {
            const float4* srcp = (const float4*)(node_feat + (size_t)sSrcW[i] * NF);
            float4 x = __ldg(&srcp[lane]);
            xhA[i] = make_uint2(pack_h2(x.x, x.y), pack_h2(x.z, x.w));
        }

        // ---- GEMM3: (16x32)@(32x128) -> +bias -> per-warp SW (fp16) ----
        // (SE region dead: A1 consumed; SW overwrites it)
        #pragma unroll
        for (int j = 0; j < 16; j++) {
            float c[4] = {0,0,0,0};
            #pragma unroll
            for (int kk = 0; kk < 2; kk++) {
                uint2 b = ((const uint2*)&sm[OFF_FB3])[(kk*16 + j)*32 + lane];
                mma_f16(c, A3[kk][0], A3[kk][1], A3[kk][2], A3[kk][3], b.x, b.y);
            }
            float2 bb = *(const float2*)&sm[OFF_B3 + 8*j + 2*tig];
            SWp[g*SW_WSTR + 4*j + tig]     = pack_h2(c[0] + bb.x, c[1] + bb.y);
            SWp[(g+8)*SW_WSTR + 4*j + tig] = pack_h2(c[2] + bb.x, c[3] + bb.y);
        }

        // ---- second gather batch (edges 8..15) ----
        uint2 xhB[8];
        #pragma unroll
        for (int i = 0; i < 8; i++) {
            const float4* srcp = (const float4*)(node_feat + (size_t)sSrcW[8 + i] * NF);
            float4 x = __ldg(&srcp[lane]);
            xhB[i] = make_uint2(pack_h2(x.x, x.y), pack_h2(x.z, x.w));
        }
        __syncwarp();   // SW stores visible to all lanes of this warp

        // ---- message + scatter, 16 edges, two register batches ----
        #pragma unroll
        for (int half16 = 0; half16 < 2; half16++) {
            #pragma unroll
            for (int i = 0; i < 8; i++) {
                const int e = half16 * 8 + i;
                float4 ef = sEFW[e];
                const __half* W = (const __half*)(SWp + (size_t)e * SW_WSTR);
                uint2 xh = half16 ? xhB[i] : xhA[i];

                uint32_t s_u0 = __shfl_sync(0xffffffffu, xh.x, srcA);
                uint32_t s_u1 = __shfl_sync(0xffffffffu, xh.y, srcA);
                uint32_t s_v0 = __shfl_sync(0xffffffffu, xh.x, srcA + 1);
                uint32_t s_v1 = __shfl_sync(0xffffffffu, xh.y, srcA + 1);
                uint32_t s_w0 = __shfl_sync(0xffffffffu, xh.x, srcA + 2);
                uint32_t s_w1 = __shfl_sync(0xffffffffu, xh.y, srcA + 2);

                float2 own0 = h22f2(xh.x);
                float2 own1 = h22f2(xh.y);

                float4 res;
                if (lane < 8) {
                    float2 A0 = h22f2(s_u0), A1v = h22f2(s_u1);
                    float2 B0 = h22f2(s_v0), B1v = h22f2(s_v1);
                    float2 C0 = h22f2(s_w0), C1v = h22f2(s_w1);
                    float2 w0a = __half22float2(*(const __half2*)(W + c4));
                    float2 w0b = __half22float2(*(const __half2*)(W + c4 + 2));
                    float2 w1a = __half22float2(*(const __half2*)(W + 96 + c4));
                    float2 w1b = __half22float2(*(const __half2*)(W + 96 + c4 + 2));
                    float d0 = A0.x*ef.y + A0.y*ef.z + A1v.x*ef.w;
                    float d1 = A1v.y*ef.y + B0.x*ef.z + B0.y*ef.w;
                    float d2 = B1v.x*ef.y + B1v.y*ef.z + C0.x*ef.w;
                    float d3 = C0.y*ef.y + C1v.x*ef.z + C1v.y*ef.w;
                    res.x = S2_C * w0a.x * own0.x * ef.x + S2_3_C * w1a.x * d0;
                    res.y = S2_C * w0a.y * own0.y * ef.x + S2_3_C * w1a.y * d1;
                    res.z = S2_C * w0b.x * own1.x * ef.x + S2_3_C * w1b.x * d2;
                    res.w = S2_C * w0b.y * own1.y * ef.x + S2_3_C * w1b.y * d3;
                } else {
                    float2 U0 = h22f2(s_u0), U1 = h22f2(s_u1), V0 = h22f2(s_v0);
                    float x0a = (selid == 0) ? U0.x : (selid == 1) ? U0.y : (selid == 2) ? U1.x : U1.y;
                    float x0b = (selid == 0) ? U0.y : (selid == 1) ? U1.x : (selid == 2) ? U1.y : V0.x;
                    float w011a = __half2float(W[32 + ua]);
                    float w011b = __half2float(W[33 + ua]);
                    float w101a = __half2float(W[64 + ua]);
                    float w101b = __half2float(W[65 + ua]);
                    float xs[4] = {own0.x, own0.y, own1.x, own1.y};
                    float s2e0 = S2_C * ef.x;
                    float r[4];
                    #pragma unroll
                    for (int i2 = 0; i2 < 4; i2++) {
                        int jj = j0 + i2;               // 0..5; no division
                        bool hi = (jj >= 3);
                        int j = hi ? (jj - 3) : jj;
                        float e1j = (j == 0) ? ef.y : ((j == 1) ? ef.z : ef.w);
                        float w011 = hi ? w011b : w011a;
                        float w101 = hi ? w101b : w101a;
                        float x0u  = hi ? x0b  : x0a;
                        r[i2] = S2_C * w011 * x0u * e1j + w101 * xs[i2] * s2e0;
                    }
                    res = make_float4(r[0], r[1], r[2], r[3]);
                }
                float4* dstp = (float4*)(out + (size_t)sDstW[e] * NF + c4);
                atomicAdd(dstp, res);
            }
        }
        __syncwarp();   // message reads of SW/idx done before next tile overwrites
    }
}

// ---- zero-init for atomic accumulation ----
__global__ void tfn_zero_kernel(float4* __restrict__ out) {
    int i = blockIdx.x * blockDim.x + threadIdx.x;   // 6250*256 = 1.6M exactly
    out[i] = make_float4(0.f, 0.f, 0.f, 0.f);
}

extern "C" void kernel_launch(void* const* d_in, const int* in_sizes, int n_in,
                              void* d_out, int out_size)
{
    const int*   edge_index = (const int*)d_in[0];
    const float* node_feat  = (const float*)d_in[1];
    const float* edge_feat  = (const float*)d_in[2];
    const float* edge_embed = (const float*)d_in[3];
    const float* fc_w1 = (const float*)d_in[4];
    const float* fc_b1 = (const float*)d_in[5];
    const float* fc_w2 = (const float*)d_in[6];
    const float* fc_b2 = (const float*)d_in[7];
    const float* fc_w3 = (const float*)d_in[8];
    const float* fc_b3 = (const float*)d_in[9];
    const float* sc_w0 = (const float*)d_in[10];
    const float* sc_w1 = (const float*)d_in[11];
    float* out = (float*)d_out;

    tfn_zero_kernel<<<6250, 256>>>((float4*)out);

    const size_t smem_bytes = SMEM_WORDS * sizeof(float);
    cudaFuncSetAttribute(tfn_fused_kernel,
                         cudaFuncAttributeMaxDynamicSharedMemorySize,
                         (int)smem_bytes);
    tfn_fused_kernel<<<GRID, NTHREADS, smem_bytes>>>(
        edge_index, node_feat, edge_feat, edge_embed,
        fc_w1, fc_b1, fc_w2, fc_b2, fc_w3, fc_b3,
        sc_w0, sc_w1, out);
}

// round 17
// speedup vs baseline: 1.2110x; 1.2110x over previous
#include <cuda_runtime.h>
#include <cuda_fp16.h>
#include <cstdint>

#define N_NODES 50000
#define N_EDGES 800000
#define NF 128
#define TILE 64
#define NTHREADS 256
#define NTILES (N_EDGES / TILE)   // 12500 exactly
#define GRID 608                  // 4 CTAs/SM x 152 SMs

#define S2_C 0.7071067811865475f
#define S2_3_C 0.4082482904638631f
#define INV_SQRT_MUL_C 0.17677669529663687f

// ---- shared memory layout (32-bit word offsets) ----
#define OFF_FB1 0            // 2kk x 8jg x 32 lanes x uint2  = 1024 words
#define OFF_FB2 1024         // 4kk x 4jg x 32 x uint2        = 1024
#define OFF_FB3 2048         // 2kk x 16jg x 32 x uint2       = 2048 -> 4096
#define OFF_B1  4096         // 64 f32
#define OFF_B2  4160         // 32 f32
#define OFF_B3  4192         // 128 f32 -> 4320
// fp16 activations, word strides == 4 (mod 8) -> conflict-free frag access
#define SE_WSTR  20
#define SH1_WSTR 36
#define SH2_WSTR 20
#define SW_WSTR  68
#define OFF_SE  4320                      // 64 x 20 = 1280 -> 5600
#define OFF_SH1 5600                      // 64 x 36 = 2304 -> 7904
#define OFF_SH2 7904                      // 64 x 20 = 1280 -> 9184
#define OFF_SW  9184                      // 64 x 68 = 4352 -> 13536 (also sc f32 scratch)
#define OFF_SRC 13536                     // 2 x 64 ints
#define OFF_DST 13664                     // 2 x 64 ints
#define OFF_EF  13792                     // 2 x 64 x 4 f32 -> 14304
#define SMEM_WORDS 14304                  // 57.2 KB -> 4 CTAs/SM (with 64-reg cap)

#define BARH(h) asm volatile("bar.sync %0, %1;" :: "r"(3 + (h)), "r"(128) : "memory")

// silu(x) = x*sigmoid(x) = hx + hx*tanh(hx), hx = x/2  (1 MUFU instead of 2)
__device__ __forceinline__ float silu_f(float x) {
    float hx = 0.5f * x;
    float th;
    asm("tanh.approx.f32 %0, %1;" : "=f"(th) : "f"(hx));
    return fmaf(hx, th, hx);
}

__device__ __forceinline__ uint32_t pack_h2(float a, float b) {
    __half2 h = __floats2half2_rn(a, b);
    return *reinterpret_cast<uint32_t*>(&h);
}

__device__ __forceinline__ float2 h22f2(uint32_t u) {
    return __half22float2(*reinterpret_cast<__half2*>(&u));
}

__device__ __forceinline__ void mma_f16(float c[4],
                                        uint32_t a0, uint32_t a1, uint32_t a2, uint32_t a3,
                                        uint32_t b0, uint32_t b1) {
    asm volatile("mma.sync.aligned.m16n8k16.row.col.f32.f16.f16.f32 "
                 "{%0,%1,%2,%3},{%4,%5,%6,%7},{%8,%9},{%0,%1,%2,%3};"
                 : "+f"(c[0]), "+f"(c[1]), "+f"(c[2]), "+f"(c[3])
                 : "r"(a0), "r"(a1), "r"(a2), "r"(a3), "r"(b0), "r"(b1));
}

extern __shared__ float sm[];

__global__ __launch_bounds__(NTHREADS, 4)
void tfn_fused_kernel(const int* __restrict__ edge_index,
                      const float* __restrict__ node_feat,
                      const float* __restrict__ edge_feat,
                      const float* __restrict__ edge_embed,
                      const float* __restrict__ w1, const float* __restrict__ b1,
                      const float* __restrict__ w2, const float* __restrict__ b2,
                      const float* __restrict__ w3, const float* __restrict__ b3,
                      const float* __restrict__ sc_w0,
                      const float* __restrict__ sc_w1,
                      float* __restrict__ out)
{
    const int t = threadIdx.x;
    const int w = t >> 5, lane = t & 31;
    const int g = lane >> 2, tig = lane & 3;
    const int mr = w >> 2;          // half id (row-group of 32 edges)
    const int nq = w & 3;           // warp-in-half (col-group)
    const int lt = t & 127;         // thread id within half
    uint32_t* smu = (uint32_t*)sm;

    // ---- precompute fp16 B-fragments (once per CTA) ----
    for (int i = t; i < 512; i += NTHREADS) {        // W1: 32x64, kk 0..1, jg 0..7
        int kk = i >> 8, jg = (i >> 5) & 7, ln = i & 31;
        int gg = ln >> 2, tt = ln & 3;
        int k0 = 16*kk + 2*tt, n = 8*jg + gg;
        ((uint2*)&sm[OFF_FB1])[i] = make_uint2(
            pack_h2(w1[k0*64 + n],     w1[(k0+1)*64 + n]),
            pack_h2(w1[(k0+8)*64 + n], w1[(k0+9)*64 + n]));
    }
    for (int i = t; i < 512; i += NTHREADS) {        // W2: 64x32, kk 0..3, jg 0..3
        int kk = i >> 7, jg = (i >> 5) & 3, ln = i & 31;
        int gg = ln >> 2, tt = ln & 3;
        int k0 = 16*kk + 2*tt, n = 8*jg + gg;
        ((uint2*)&sm[OFF_FB2])[i] = make_uint2(
            pack_h2(w2[k0*32 + n],     w2[(k0+1)*32 + n]),
            pack_h2(w2[(k0+8)*32 + n], w2[(k0+9)*32 + n]));
    }
    for (int i = t; i < 1024; i += NTHREADS) {       // W3: 32x128, kk 0..1, jg 0..15
        int kk = i >> 9, jg = (i >> 5) & 15, ln = i & 31;
        int gg = ln >> 2, tt = ln & 3;
        int k0 = 16*kk + 2*tt, n = 8*jg + gg;
        ((uint2*)&sm[OFF_FB3])[i] = make_uint2(
            pack_h2(w3[k0*128 + n],     w3[(k0+1)*128 + n]),
            pack_h2(w3[(k0+8)*128 + n], w3[(k0+9)*128 + n]));
    }
    for (int i = t; i < 64;  i += NTHREADS) sm[OFF_B1 + i] = b1[i];
    for (int i = t; i < 32;  i += NTHREADS) sm[OFF_B2 + i] = b2[i];
    for (int i = t; i < 128; i += NTHREADS) sm[OFF_B3 + i] = b3[i];

    // ---- fused self-connection pass (atomic adds onto zeroed out) ----
    {
        const int half = t >> 7, ct = t & 127;
        float wreg[32]; int jsc = 0;
        if (ct < 32) {
            #pragma unroll
            for (int u = 0; u < 32; u++) wreg[u] = sc_w0[u * 32 + ct];
        } else {
            int m = ct - 32;
            int v = m / 3;
            jsc = m - 3 * v;
            #pragma unroll
            for (int u = 0; u < 32; u++) wreg[u] = sc_w1[u * 32 + v];
        }
        float* sxb = &sm[OFF_SW + half * 128];   // SW unused until first GEMM3
        const int bid1 = 1 + half;
        for (int n = 2 * (int)blockIdx.x + half; n < N_NODES; n += 2 * (int)gridDim.x) {
            asm volatile("bar.sync %0, %1;" :: "r"(bid1), "r"(128) : "memory");
            sxb[ct] = node_feat[(size_t)n * NF + ct];
            asm volatile("bar.sync %0, %1;" :: "r"(bid1), "r"(128) : "memory");
            float acc = 0.0f;
            if (ct < 32) {
                #pragma unroll
                for (int u = 0; u < 32; u++) acc += sxb[u] * wreg[u];
            } else {
                #pragma unroll
                for (int u = 0; u < 32; u++) acc += sxb[32 + 3*u + jsc] * wreg[u];
            }
            atomicAdd(&out[(size_t)n * NF + ct], acc * INV_SQRT_MUL_C);
        }
    }

    int* sSrcA = (int*)&sm[OFF_SRC];     // [2][64]
    int* sDstA = (int*)&sm[OFF_DST];     // [2][64]

    // ---- prologue: prefetch tile0 (parity 0), fp16 embed (half-local rows) ----
    {
        const int t0 = blockIdx.x;
        #pragma unroll
        for (int ii = 0; ii < 2; ii++) {
            int item = lt + 128 * ii;            // 0..255 within half
            int e = 32 * mr + (item >> 3);       // own half's rows only
            int k = item & 7;
            float4 v = ((const float4*)(edge_embed + (size_t)t0 * (TILE * 32)))[8*e + k];
            *(uint2*)&smu[OFF_SE + e * SE_WSTR + 2*k] =
                make_uint2(pack_h2(v.x, v.y), pack_h2(v.z, v.w));
        }
        if (nq == 0) {
            int e2 = 32 * mr + lane;
            sSrcA[e2] = edge_index[t0 * TILE + e2];
            sDstA[e2] = edge_index[N_EDGES + t0 * TILE + e2];
            ((float4*)&sm[OFF_EF])[e2] = ((const float4*)edge_feat)[t0 * TILE + e2];
        }
    }
    __syncthreads();   // FB + tile0 visible; halves decouple after this

    // per-lane message constants
    const int c4 = 4 * lane;
    const int m0 = c4 - 32;
    const int ua = (lane >= 8) ? (m0 / 3) : 0;
    const int j0 = (lane >= 8) ? (m0 - 3 * ua) : 0;   // m0 mod 3, precomputed
    const int srcA = (lane < 8) ? (8 + 3 * lane) : (ua >> 2);
    const int selid = ua & 3;
    const int eb = 32 * mr + nq;     // this warp's first edge in its half

    int p = 0;
    const int gstride = gridDim.x;

    for (int tile = blockIdx.x; tile < NTILES; tile += gstride) {
        BARH(mr);   // A: SE + idx[p] ready for this half; prev message done

        // ---- GEMM1: (32x32)@(32x64) -> +bias -> silu -> fp16 -> sH1 (2 m-blocks) ----
        #pragma unroll
        for (int blk = 0; blk < 2; blk++) {
            const int rb = 32*mr + 16*blk;
            float c[2][4] = {{0,0,0,0},{0,0,0,0}};
            #pragma unroll
            for (int kk = 0; kk < 2; kk++) {
                const uint32_t* Ab = &smu[OFF_SE + (rb + g) * SE_WSTR + 8*kk + tig];
                uint32_t a0 = Ab[0];
                uint32_t a1 = Ab[8*SE_WSTR];
                uint32_t a2 = Ab[4];
                uint32_t a3 = Ab[8*SE_WSTR + 4];
                #pragma unroll
                for (int j = 0; j < 2; j++) {
                    uint2 b = ((const uint2*)&sm[OFF_FB1])[(kk*8 + 2*nq + j)*32 + lane];
                    mma_f16(c[j], a0, a1, a2, a3, b.x, b.y);
                }
            }
            #pragma unroll
            for (int j = 0; j < 2; j++) {
                int n0 = 16*nq + 8*j + 2*tig;
                float2 bb = *(const float2*)&sm[OFF_B1 + n0];
                int wi = 8*nq + 4*j + tig;
                smu[OFF_SH1 + (rb+g)*SH1_WSTR + wi] =
                    pack_h2(silu_f(c[j][0] + bb.x), silu_f(c[j][1] + bb.y));
                smu[OFF_SH1 + (rb+g+8)*SH1_WSTR + wi] =
                    pack_h2(silu_f(c[j][2] + bb.x), silu_f(c[j][3] + bb.y));
            }
        }
        BARH(mr);   // B

        // ---- GEMM2: (32x64)@(64x32) -> +bias -> silu -> fp16 -> sH2 (2 m-blocks) ----
        #pragma unroll
        for (int blk = 0; blk < 2; blk++) {
            const int rb = 32*mr + 16*blk;
            float ca[4] = {0,0,0,0}, cb[4] = {0,0,0,0};
            #pragma unroll
            for (int k2 = 0; k2 < 2; k2++) {
                {
                    const int kk = 2*k2;
                    const uint32_t* Ab = &smu[OFF_SH1 + (rb + g) * SH1_WSTR + 8*kk + tig];
                    uint2 b = ((const uint2*)&sm[OFF_FB2])[(kk*4 + nq)*32 + lane];
                    mma_f16(ca, Ab[0], Ab[8*SH1_WSTR], Ab[4], Ab[8*SH1_WSTR + 4], b.x, b.y);
                }
                {
                    const int kk = 2*k2 + 1;
                    const uint32_t* Ab = &smu[OFF_SH1 + (rb + g) * SH1_WSTR + 8*kk + tig];
                    uint2 b = ((const uint2*)&sm[OFF_FB2])[(kk*4 + nq)*32 + lane];
                    mma_f16(cb, Ab[0], Ab[8*SH1_WSTR], Ab[4], Ab[8*SH1_WSTR + 4], b.x, b.y);
                }
            }
            int n0 = 8*nq + 2*tig;
            float2 bb = *(const float2*)&sm[OFF_B2 + n0];
            int wi = 4*nq + tig;
            smu[OFF_SH2 + (rb+g)*SH2_WSTR + wi] =
                pack_h2(silu_f(ca[0] + cb[0] + bb.x), silu_f(ca[1] + cb[1] + bb.y));
            smu[OFF_SH2 + (rb+g+8)*SH2_WSTR + wi] =
                pack_h2(silu_f(ca[2] + cb[2] + bb.x), silu_f(ca[3] + cb[3] + bb.y));
        }
        BARH(mr);   // C

        // ---- GEMM3 + first gather batch (packed fp16 in registers) ----
        uint2 xhA[4];
        {
            #pragma unroll
            for (int i = 0; i < 4; i++) {
                const float4* srcp = (const float4*)(node_feat + (size_t)sSrcA[p*64 + eb + 4*i] * NF);
                float4 x = __ldg(&srcp[lane]);
                xhA[i] = make_uint2(pack_h2(x.x, x.y), pack_h2(x.z, x.w));
            }

            #pragma unroll
            for (int blk = 0; blk < 2; blk++) {
                const int rb = 32*mr + 16*blk;
                uint32_t Af[2][4];
                #pragma unroll
                for (int kk = 0; kk < 2; kk++) {
                    const uint32_t* Ab = &smu[OFF_SH2 + (rb + g) * SH2_WSTR + 8*kk + tig];
                    Af[kk][0] = Ab[0];
                    Af[kk][1] = Ab[8*SH2_WSTR];
                    Af[kk][2] = Ab[4];
                    Af[kk][3] = Ab[8*SH2_WSTR + 4];
                }
                #pragma unroll
                for (int j = 0; j < 4; j++) {
                    float c[4] = {0,0,0,0};
                    #pragma unroll
                    for (int kk = 0; kk < 2; kk++) {
                        uint2 b = ((const uint2*)&sm[OFF_FB3])[(kk*16 + 4*nq + j)*32 + lane];
                        mma_f16(c, Af[kk][0], Af[kk][1], Af[kk][2], Af[kk][3], b.x, b.y);
                    }
                    int n0 = 32*nq + 8*j + 2*tig;
                    float2 bb = *(const float2*)&sm[OFF_B3 + n0];
                    int wi = 16*nq + 4*j + tig;
                    smu[OFF_SW + (rb+g)*SW_WSTR + wi] = pack_h2(c[0] + bb.x, c[1] + bb.y);
                    smu[OFF_SW + (rb+g+8)*SW_WSTR + wi] = pack_h2(c[2] + bb.x, c[3] + bb.y);
                }
            }
        }
        BARH(mr);   // D

        // ---- message + scatter + next-tile prefetch (8 edges per warp) ----
        {
            const int tn = tile + gstride;
            const bool pf = (tn < NTILES);
            float4 emb[2];
            if (pf) {
                #pragma unroll
                for (int ii = 0; ii < 2; ii++) {
                    int item = lt + 128 * ii;
                    int e = 32 * mr + (item >> 3);
                    int k = item & 7;
                    emb[ii] = ((const float4*)(edge_embed + (size_t)tn * (TILE * 32)))[8*e + k];
                }
            }

            // second gather batch (latency hidden behind first 4 edges' message work)
            uint2 xhB[4];
            #pragma unroll
            for (int i = 0; i < 4; i++) {
                const float4* srcp = (const float4*)(node_feat + (size_t)sSrcA[p*64 + eb + 4*(i+4)] * NF);
                float4 x = __ldg(&srcp[lane]);
                xhB[i] = make_uint2(pack_h2(x.x, x.y), pack_h2(x.z, x.w));
            }

            #pragma unroll
            for (int i = 0; i < 8; i++) {
                const int e = eb + 4*i;
                float4 ef = ((const float4*)&sm[OFF_EF + p*256])[e];
                const __half* W = (const __half*)&smu[OFF_SW + e * SW_WSTR];
                uint2 xh = (i < 4) ? xhA[i & 3] : xhB[i & 3];

                uint32_t s_u0 = __shfl_sync(0xffffffffu, xh.x, srcA);
                uint32_t s_u1 = __shfl_sync(0xffffffffu, xh.y, srcA);
                uint32_t s_v0 = __shfl_sync(0xffffffffu, xh.x, srcA + 1);
                uint32_t s_v1 = __shfl_sync(0xffffffffu, xh.y, srcA + 1);
                uint32_t s_w0 = __shfl_sync(0xffffffffu, xh.x, srcA + 2);
                uint32_t s_w1 = __shfl_sync(0xffffffffu, xh.y, srcA + 2);

                float2 own0 = h22f2(xh.x);
                float2 own1 = h22f2(xh.y);

                float4 res;
                if (lane < 8) {
                    float2 A0 = h22f2(s_u0), A1 = h22f2(s_u1);
                    float2 B0 = h22f2(s_v0), B1 = h22f2(s_v1);
                    float2 C0 = h22f2(s_w0), C1 = h22f2(s_w1);
                    uint2 wv0 = *(const uint2*)(W + c4);        // w000[c..c+3]
                    uint2 wv1 = *(const uint2*)(W + 96 + c4);   // w110[c..c+3]
                    float2 w0a = h22f2(wv0.x), w0b = h22f2(wv0.y);
                    float2 w1a = h22f2(wv1.x), w1b = h22f2(wv1.y);
                    float d0 = A0.x*ef.y + A0.y*ef.z + A1.x*ef.w;
                    float d1 = A1.y*ef.y + B0.x*ef.z + B0.y*ef.w;
                    float d2 = B1.x*ef.y + B1.y*ef.z + C0.x*ef.w;
                    float d3 = C0.y*ef.y + C1.x*ef.z + C1.y*ef.w;
                    res.x = S2_C * w0a.x * own0.x * ef.x + S2_3_C * w1a.x * d0;
                    res.y = S2_C * w0a.y * own0.y * ef.x + S2_3_C * w1a.y * d1;
                    res.z = S2_C * w0b.x * own1.x * ef.x + S2_3_C * w1b.x * d2;
                    res.w = S2_C * w0b.y * own1.y * ef.x + S2_3_C * w1b.y * d3;
                } else {
                    float2 U0 = h22f2(s_u0), U1 = h22f2(s_u1), V0 = h22f2(s_v0);
                    float x0a = (selid == 0) ? U0.x : (selid == 1) ? U0.y : (selid == 2) ? U1.x : U1.y;
                    float x0b = (selid == 0) ? U0.y : (selid == 1) ? U1.x : (selid == 2) ? U1.y : V0.x;
                    float w011a = __half2float(W[32 + ua]);
                    float w011b = __half2float(W[33 + ua]);
                    float w101a = __half2float(W[64 + ua]);
                    float w101b = __half2float(W[65 + ua]);
                    float xs[4] = {own0.x, own0.y, own1.x, own1.y};
                    float s2e0 = S2_C * ef.x;
                    float r[4];
                    #pragma unroll
                    for (int i2 = 0; i2 < 4; i2++) {
                        int jj = j0 + i2;               // 0..5; no division
                        bool hi = (jj >= 3);
                        int j = hi ? (jj - 3) : jj;
                        float e1j = (j == 0) ? ef.y : ((j == 1) ? ef.z : ef.w);
                        float w011 = hi ? w011b : w011a;
                        float w101 = hi ? w101b : w101a;
                        float x0u  = hi ? x0b  : x0a;
                        r[i2] = S2_C * w011 * x0u * e1j + w101 * xs[i2] * s2e0;
                    }
                    res = make_float4(r[0], r[1], r[2], r[3]);
                }
                float4* dstp = (float4*)(out + (size_t)sDstA[p*64 + e] * NF + c4);
                atomicAdd(dstp, res);
            }

            if (pf) {
                #pragma unroll
                for (int ii = 0; ii < 2; ii++) {
                    int item = lt + 128 * ii;
                    int e = 32 * mr + (item >> 3);
                    int k = item & 7;
                    *(uint2*)&smu[OFF_SE + e * SE_WSTR + 2*k] =
                        make_uint2(pack_h2(emb[ii].x, emb[ii].y), pack_h2(emb[ii].z, emb[ii].w));
                }
                if (nq == 0) {
                    int q2 = p ^ 1;
                    int e2 = 32 * mr + lane;
                    sSrcA[q2*64 + e2] = edge_index[tn * TILE + e2];
                    sDstA[q2*64 + e2] = edge_index[N_EDGES + tn * TILE + e2];
                    ((float4*)&sm[OFF_EF + q2*256])[e2] = ((const float4*)edge_feat)[tn * TILE + e2];
                }
            }
        }
        p ^= 1;
    }
}

// ---- zero-init for atomic accumulation ----
__global__ void tfn_zero_kernel(float4* __restrict__ out) {
    int i = blockIdx.x * blockDim.x + threadIdx.x;   // 6250*256 = 1.6M exactly
    out[i] = make_float4(0.f, 0.f, 0.f, 0.f);
}

extern "C" void kernel_launch(void* const* d_in, const int* in_sizes, int n_in,
                              void* d_out, int out_size)
{
    const int*   edge_index = (const int*)d_in[0];
    const float* node_feat  = (const float*)d_in[1];
    const float* edge_feat  = (const float*)d_in[2];
    const float* edge_embed = (const float*)d_in[3];
    const float* fc_w1 = (const float*)d_in[4];
    const float* fc_b1 = (const float*)d_in[5];
    const float* fc_w2 = (const float*)d_in[6];
    const float* fc_b2 = (const float*)d_in[7];
    const float* fc_w3 = (const float*)d_in[8];
    const float* fc_b3 = (const float*)d_in[9];
    const float* sc_w0 = (const float*)d_in[10];
    const float* sc_w1 = (const float*)d_in[11];
    float* out = (float*)d_out;

    tfn_zero_kernel<<<6250, 256>>>((float4*)out);

    const size_t smem_bytes = SMEM_WORDS * sizeof(float);
    cudaFuncSetAttribute(tfn_fused_kernel,
                         cudaFuncAttributeMaxDynamicSharedMemorySize,
                         (int)smem_bytes);
    tfn_fused_kernel<<<GRID, NTHREADS, smem_bytes>>>(
        edge_index, node_feat, edge_feat, edge_embed,
        fc_w1, fc_b1, fc_w2, fc_b2, fc_w3, fc_b3,
        sc_w0, sc_w1, out);
}